// round 15
// baseline (speedup 1.0000x reference)
#include <cuda_runtime.h>
#include <cuda_fp16.h>
#include <cstdint>
#include <cstddef>

#define N_USERS 50000
#define N_PRODS 50000
#define NN      100000
#define NE      600000
#define HDIM    128
#define ODIM    16
#define NBLK1   98        // ceil(NN/1024)

// Scratch (__device__ globals: allocation-free rule)
__device__ __half   g_x[(size_t)NN * HDIM];    // input-transform output
__device__ __half   g_ya[(size_t)NN * HDIM];   // layer ping
__device__ __half   g_yb[(size_t)NN * HDIM];   // layer pong
__device__ float    g_dinv[NN];
__device__ int      g_deg[NN];
__device__ int      g_rowstart[NN + 1];
__device__ int      g_cursor[NN];
__device__ int      g_esrc[NE];
__device__ int      g_blksum[NBLK1];
__device__ int      g_is64;
// f16 B fragments: Wu@0(4096), Wp@4096(7168), W1@11264, W2@19456, W3@27648 (8192 ea), Wo@35840(1024)
__device__ uint32_t g_wfrag[36864];

#define OFF_WU 0
#define OFF_WP 4096
#define OFF_W1 11264
#define OFF_W2 19456
#define OFF_W3 27648
#define OFF_WO 35840

// Side stream + events for CSR overlap (static-init; reused -> deterministic).
struct SideStream {
    cudaStream_t s = nullptr;
    cudaEvent_t evFork = nullptr, evJoin = nullptr;
    SideStream() {
        cudaStreamCreateWithFlags(&s, cudaStreamNonBlocking);
        cudaEventCreateWithFlags(&evFork, cudaEventDisableTiming);
        cudaEventCreateWithFlags(&evJoin, cudaEventDisableTiming);
    }
};
static SideStream g_side;

// ---------------------------------------------------------------------------
// helpers (sm_80-class PTX only)
// ---------------------------------------------------------------------------
__device__ __forceinline__ uint32_t packh2(float lo, float hi) {
    __half2 h = __floats2half2_rn(lo, hi);
    return *reinterpret_cast<uint32_t*>(&h);
}
__device__ __forceinline__ void mma_f16(float* c, const uint32_t* a, const uint32_t* b) {
    asm volatile(
        "mma.sync.aligned.m16n8k16.row.col.f32.f16.f16.f32 "
        "{%0,%1,%2,%3}, {%4,%5,%6,%7}, {%8,%9}, {%0,%1,%2,%3};"
        : "+f"(c[0]), "+f"(c[1]), "+f"(c[2]), "+f"(c[3])
        : "r"(a[0]), "r"(a[1]), "r"(a[2]), "r"(a[3]), "r"(b[0]), "r"(b[1]));
}
__device__ __forceinline__ void h4_to_f4(uint2 t, float4& f) {
    float2 a = __half22float2(*reinterpret_cast<__half2*>(&t.x));
    float2 b = __half22float2(*reinterpret_cast<__half2*>(&t.y));
    f.x = a.x; f.y = a.y; f.z = b.x; f.w = b.y;
}

// ---------------------------------------------------------------------------
// Gather one node's row (128 cols; this lane covers cols lane*4..lane*4+3)
// from ysrc via CSR, apply self-loop+sym-norm+bias+relu, return packed f16x4.
// ---------------------------------------------------------------------------
__device__ __forceinline__ uint2 gather_node(
    const __half* __restrict__ ysrc, const float* __restrict__ bias, int node, int lane)
{
    const int co = lane * 4;
    float dd = g_dinv[node];
    float4 acc;
    {
        uint2 t = *(const uint2*)&ysrc[(size_t)node * HDIM + co];
        h4_to_f4(t, acc);
        acc.x *= dd; acc.y *= dd; acc.z *= dd; acc.w *= dd;
    }
    int e = g_rowstart[node];
    const int end = g_rowstart[node + 1];
    for (; e + 4 <= end; e += 4) {
        int s0 = g_esrc[e], s1 = g_esrc[e + 1], s2 = g_esrc[e + 2], s3 = g_esrc[e + 3];
        float n0 = g_dinv[s0], n1 = g_dinv[s1], n2 = g_dinv[s2], n3 = g_dinv[s3];
        uint2 t0 = *(const uint2*)&ysrc[(size_t)s0 * HDIM + co];
        uint2 t1 = *(const uint2*)&ysrc[(size_t)s1 * HDIM + co];
        uint2 t2 = *(const uint2*)&ysrc[(size_t)s2 * HDIM + co];
        uint2 t3 = *(const uint2*)&ysrc[(size_t)s3 * HDIM + co];
        float4 a, b, c, d;
        h4_to_f4(t0, a); h4_to_f4(t1, b); h4_to_f4(t2, c); h4_to_f4(t3, d);
        acc.x += a.x * n0 + b.x * n1 + c.x * n2 + d.x * n3;
        acc.y += a.y * n0 + b.y * n1 + c.y * n2 + d.y * n3;
        acc.z += a.z * n0 + b.z * n1 + c.z * n2 + d.z * n3;
        acc.w += a.w * n0 + b.w * n1 + c.w * n2 + d.w * n3;
    }
    for (; e < end; e++) {
        int s = g_esrc[e];
        float ns = g_dinv[s];
        uint2 t = *(const uint2*)&ysrc[(size_t)s * HDIM + co];
        float4 a; h4_to_f4(t, a);
        acc.x += a.x * ns; acc.y += a.y * ns; acc.z += a.z * ns; acc.w += a.w * ns;
    }
    float4 bb = *(const float4*)&bias[co];
    uint2 o;
    o.x = packh2(fmaxf(acc.x * dd + bb.x, 0.f), fmaxf(acc.y * dd + bb.y, 0.f));
    o.y = packh2(fmaxf(acc.z * dd + bb.z, 0.f), fmaxf(acc.w * dd + bb.w, 0.f));
    return o;
}

// ---------------------------------------------------------------------------
// Precompute f16 B fragments for all 6 weights.
// m16n8k16 B tile word w: reg=w&1, lane=w>>1, n'=lane>>2, tg=lane&3;
// word = {B[tg*2+reg*8][n'], B[tg*2+1+reg*8][n']}. Tile (k16,nt) at (k16*NT+nt)*64.
// ---------------------------------------------------------------------------
__global__ __launch_bounds__(256) void k_wfrag(
    const float* __restrict__ Wu, const float* __restrict__ Wp,
    const float* __restrict__ W1, const float* __restrict__ W2,
    const float* __restrict__ W3, const float* __restrict__ Wo)
{
    const int nblk[6] = {4, 7, 8, 8, 8, 1};
    const int offs[6] = {OFF_WU, OFF_WP, OFF_W1, OFF_W2, OFF_W3, OFF_WO};
    const int kds[6]  = {64, 100, 128, 128, 128, 128};
    int b = blockIdx.x, slot = 0;
    while (slot < 6 && b >= nblk[slot]) { b -= nblk[slot]; slot++; }
    if (slot >= 6) return;
    const float* W = (slot == 0) ? Wu : (slot == 1) ? Wp : (slot == 2) ? W1
                   : (slot == 3) ? W2 : (slot == 4) ? W3 : Wo;
    const int Kdim = kds[slot];
    uint32_t* dst = g_wfrag + offs[slot];
    if (slot < 5) {
#pragma unroll
        for (int i = 0; i < 4; i++) {
            int w = b * 1024 + threadIdx.x + i * 256;
            int nt = (w >> 6) & 15;
            int widx = w & 63;
            int reg = widx & 1, lane = widx >> 1;
            int n = nt * 8 + (lane >> 2), tg = lane & 3;
            int k = (w >> 10) * 16 + tg * 2 + reg * 8;
            float lo = (k     < Kdim) ? W[(size_t)k * HDIM + n] : 0.f;
            float hi = (k + 1 < Kdim) ? W[(size_t)(k + 1) * HDIM + n] : 0.f;
            dst[w] = packh2(lo, hi);
        }
    } else {
#pragma unroll
        for (int i = 0; i < 4; i++) {
            int w = threadIdx.x + i * 256;
            int k16 = w >> 7, r = w & 127;
            int nt = (r >> 6) & 1;
            int widx = r & 63;
            int reg = widx & 1, lane = widx >> 1;
            int n = nt * 8 + (lane >> 2), tg = lane & 3;
            int k = k16 * 16 + tg * 2 + reg * 8;
            dst[w] = packh2(W[(size_t)k * ODIM + n], W[(size_t)(k + 1) * ODIM + n]);
        }
    }
}

// ---------------------------------------------------------------------------
// Plain f16 GEMM (R12 config): 256 thr, 128x128 CTA, warp tile 32x64.
// Used for input transforms (F32IN) and layer-1 (fp16 A from g_x).
// ---------------------------------------------------------------------------
template<int K16, int SW, bool F32IN, int KDIM>
__global__ __launch_bounds__(256, 2) void k_gemm(
    const void* __restrict__ Av, int M,
    const uint32_t* __restrict__ Bfrag, const float* __restrict__ bias,
    __half* __restrict__ out)
{
    extern __shared__ uint32_t smem[];
    uint32_t* sA = smem;
    uint32_t* sB = smem + 128 * SW;

    const int tid = threadIdx.x;
    const int wid = tid >> 5;
    const int lane = tid & 31;
    const int m0 = blockIdx.x * 128;
    const int wm = wid & 3;
    const int wn = wid >> 2;
    const int g = lane >> 2, tg = lane & 3;

#pragma unroll
    for (int it = 0; it < K16; it++) {
        int idx = tid + it * 256;
        ((uint4*)sB)[idx] = ((const uint4*)Bfrag)[idx];
    }

    if (F32IN) {
        const float* A = (const float*)Av;
        constexpr int KPAD = K16 * 16;
        constexpr int NC4 = KPAD / 4;
#pragma unroll
        for (int it = 0; it < 128 * NC4 / 256; it++) {
            int idx4 = tid + it * 256;
            int r = idx4 / NC4;
            int c4 = (idx4 - r * NC4) * 4;
            int gm = m0 + r;
            float4 v = make_float4(0.f, 0.f, 0.f, 0.f);
            if (gm < M && c4 < KDIM)
                v = *(const float4*)&A[(size_t)gm * KDIM + c4];
            uint32_t* p = sA + r * SW + c4 / 2;
            p[0] = packh2(v.x, v.y);
            p[1] = packh2(v.z, v.w);
        }
    } else {
        const __half* A = (const __half*)Av;
#pragma unroll
        for (int it = 0; it < 8; it++) {
            int idx = tid + it * 256;
            int r = idx >> 4, u = idx & 15;
            int gm = m0 + r;
            uint4 v = make_uint4(0u, 0u, 0u, 0u);
            if (gm < M) v = *(const uint4*)&A[(size_t)gm * HDIM + u * 8];
            *(uint4*)(sA + r * SW + u * 4) = v;
        }
    }
    __syncthreads();

    float acc[2][8][4];
#pragma unroll
    for (int mt = 0; mt < 2; mt++)
#pragma unroll
        for (int nt = 0; nt < 8; nt++)
#pragma unroll
            for (int j = 0; j < 4; j++) acc[mt][nt][j] = 0.f;

    const uint32_t* sAr = sA + (wm * 32 + g) * SW + tg;
    const uint2* Bw = (const uint2*)(sB + (wn * 8) * 64) + lane;

#pragma unroll
    for (int k16 = 0; k16 < K16; k16++) {
        const int c0 = k16 * 8;
        uint32_t a[2][4];
#pragma unroll
        for (int mt = 0; mt < 2; mt++) {
            const uint32_t* p = sAr + mt * 16 * SW;
            a[mt][0] = p[c0];
            a[mt][1] = p[8 * SW + c0];
            a[mt][2] = p[c0 + 4];
            a[mt][3] = p[8 * SW + c0 + 4];
        }
        uint32_t b[8][2];
#pragma unroll
        for (int nt = 0; nt < 8; nt++) {
            uint2 t = Bw[(k16 * 16 + nt) * 32];
            b[nt][0] = t.x; b[nt][1] = t.y;
        }
#pragma unroll
        for (int mt = 0; mt < 2; mt++)
#pragma unroll
            for (int nt = 0; nt < 8; nt++)
                mma_f16(acc[mt][nt], a[mt], b[nt]);
    }

    const int rbase = m0 + wm * 32 + g;
#pragma unroll
    for (int mt = 0; mt < 2; mt++) {
        int r0 = rbase + mt * 16;
        int r1 = r0 + 8;
#pragma unroll
        for (int nt = 0; nt < 8; nt++) {
            int col = wn * 64 + nt * 8 + tg * 2;
            float bx = 0.f, by = 0.f;
            if (bias) {
                float2 bb = *(const float2*)&bias[col];
                bx = bb.x; by = bb.y;
            }
            if (r0 < M)
                *(__half2*)&out[(size_t)r0 * HDIM + col] =
                    __floats2half2_rn(acc[mt][nt][0] + bx, acc[mt][nt][1] + by);
            if (r1 < M)
                *(__half2*)&out[(size_t)r1 * HDIM + col] =
                    __floats2half2_rn(acc[mt][nt][2] + bx, acc[mt][nt][3] + by);
        }
    }
}

// ---------------------------------------------------------------------------
// FUSED gather + layer GEMM: phase 1 gathers the CTA's 128 nodes (8 warps x
// 16 nodes) from ysrc (CSR, bias+relu) straight into the A SMEM tile; phase 2
// is the standard mainloop -> ydst. No g_x round trip, no A staging LDGs.
// ---------------------------------------------------------------------------
__global__ __launch_bounds__(256, 2) void k_fgemm(
    const __half* __restrict__ ysrc, const float* __restrict__ gbias,
    const uint32_t* __restrict__ Bfrag, __half* __restrict__ ydst)
{
    constexpr int SW = 68;
    extern __shared__ uint32_t smem[];
    uint32_t* sA = smem;                 // 128 * 68 words
    uint32_t* sB = smem + 128 * SW;      // 8192 words

    const int tid = threadIdx.x;
    const int wid = tid >> 5;
    const int lane = tid & 31;
    const int m0 = blockIdx.x * 128;
    const int wm = wid & 3;
    const int wn = wid >> 2;
    const int g = lane >> 2, tg = lane & 3;

    // stage B fragments
#pragma unroll
    for (int it = 0; it < 8; it++) {
        int idx = tid + it * 256;
        ((uint4*)sB)[idx] = ((const uint4*)Bfrag)[idx];
    }

    // phase 1: gather 16 nodes per warp into sA
    for (int i = 0; i < 16; i++) {
        int rloc = wid * 16 + i;
        int node = m0 + rloc;
        uint2 o = make_uint2(0u, 0u);
        if (node < NN) o = gather_node(ysrc, gbias, node, lane);
        *(uint2*)(sA + rloc * SW + lane * 2) = o;
    }
    __syncthreads();

    // phase 2: GEMM mainloop
    float acc[2][8][4];
#pragma unroll
    for (int mt = 0; mt < 2; mt++)
#pragma unroll
        for (int nt = 0; nt < 8; nt++)
#pragma unroll
            for (int j = 0; j < 4; j++) acc[mt][nt][j] = 0.f;

    const uint32_t* sAr = sA + (wm * 32 + g) * SW + tg;
    const uint2* Bw = (const uint2*)(sB + (wn * 8) * 64) + lane;

#pragma unroll
    for (int k16 = 0; k16 < 8; k16++) {
        const int c0 = k16 * 8;
        uint32_t a[2][4];
#pragma unroll
        for (int mt = 0; mt < 2; mt++) {
            const uint32_t* p = sAr + mt * 16 * SW;
            a[mt][0] = p[c0];
            a[mt][1] = p[8 * SW + c0];
            a[mt][2] = p[c0 + 4];
            a[mt][3] = p[8 * SW + c0 + 4];
        }
        uint32_t b[8][2];
#pragma unroll
        for (int nt = 0; nt < 8; nt++) {
            uint2 t = Bw[(k16 * 16 + nt) * 32];
            b[nt][0] = t.x; b[nt][1] = t.y;
        }
#pragma unroll
        for (int mt = 0; mt < 2; mt++)
#pragma unroll
            for (int nt = 0; nt < 8; nt++)
                mma_f16(acc[mt][nt], a[mt], b[nt]);
    }

    const int rbase = m0 + wm * 32 + g;
#pragma unroll
    for (int mt = 0; mt < 2; mt++) {
        int r0 = rbase + mt * 16;
        int r1 = r0 + 8;
#pragma unroll
        for (int nt = 0; nt < 8; nt++) {
            int col = wn * 64 + nt * 8 + tg * 2;
            if (r0 < NN)
                *(__half2*)&ydst[(size_t)r0 * HDIM + col] =
                    __floats2half2_rn(acc[mt][nt][0], acc[mt][nt][1]);
            if (r1 < NN)
                *(__half2*)&ydst[(size_t)r1 * HDIM + col] =
                    __floats2half2_rn(acc[mt][nt][2], acc[mt][nt][3]);
        }
    }
}

// ---------------------------------------------------------------------------
// FUSED gather + output GEMM: gather (b3+relu) -> sA, then out = sA @ Wo + bo.
// ---------------------------------------------------------------------------
__global__ __launch_bounds__(256) void k_fout(
    const __half* __restrict__ ysrc, const float* __restrict__ gbias,
    const uint32_t* __restrict__ Bfrag, const float* __restrict__ bo,
    float* __restrict__ out)
{
    constexpr int SW = 68;
    __shared__ uint32_t sA[128 * SW];
    __shared__ uint32_t sB[1024];
    const int tid = threadIdx.x;
    const int wid = tid >> 5;
    const int lane = tid & 31;
    const int m0 = blockIdx.x * 128;
    const int g = lane >> 2, tg = lane & 3;

    ((uint4*)sB)[tid] = ((const uint4*)Bfrag)[tid];

    for (int i = 0; i < 16; i++) {
        int rloc = wid * 16 + i;
        int node = m0 + rloc;
        uint2 o = make_uint2(0u, 0u);
        if (node < NN) o = gather_node(ysrc, gbias, node, lane);
        *(uint2*)(sA + rloc * SW + lane * 2) = o;
    }
    __syncthreads();

    float acc[2][4];
#pragma unroll
    for (int nt = 0; nt < 2; nt++)
#pragma unroll
        for (int j = 0; j < 4; j++) acc[nt][j] = 0.f;

    const uint32_t* sAr = sA + (wid * 16 + g) * SW + tg;
    const uint2* Bw = (const uint2*)sB + lane;

#pragma unroll
    for (int k16 = 0; k16 < 8; k16++) {
        const int c0 = k16 * 8;
        uint32_t a[4];
        a[0] = sAr[c0];
        a[1] = sAr[8 * SW + c0];
        a[2] = sAr[c0 + 4];
        a[3] = sAr[8 * SW + c0 + 4];
#pragma unroll
        for (int nt = 0; nt < 2; nt++) {
            uint2 t = Bw[(k16 * 2 + nt) * 32];
            uint32_t b[2] = {t.x, t.y};
            mma_f16(acc[nt], a, b);
        }
    }

    const int r0 = m0 + wid * 16 + g;
    const int r1 = r0 + 8;
#pragma unroll
    for (int nt = 0; nt < 2; nt++) {
        int col = nt * 8 + tg * 2;
        float2 bb = *(const float2*)&bo[col];
        if (r0 < NN) {
            out[(size_t)r0 * ODIM + col + 0] = acc[nt][0] + bb.x;
            out[(size_t)r0 * ODIM + col + 1] = acc[nt][1] + bb.y;
        }
        if (r1 < NN) {
            out[(size_t)r1 * ODIM + col + 0] = acc[nt][2] + bb.x;
            out[(size_t)r1 * ODIM + col + 1] = acc[nt][3] + bb.y;
        }
    }
}

// ---------------------------------------------------------------------------
// Edge detect + degree zero (merged) + CSR build
// ---------------------------------------------------------------------------
__global__ void k_prep(const void* __restrict__ edges) {
    int i = blockIdx.x * blockDim.x + threadIdx.x;
    if (i < NN) g_deg[i] = 0;
    if (i == 0) {
        const unsigned int* w = (const unsigned int*)edges;
        int is64 = 1;
        for (int j = 0; j < 64; j++)
            if (w[2 * j + 1] != 0u) { is64 = 0; break; }
        g_is64 = is64;
    }
}
__device__ __forceinline__ void load_edge(const void* edges, int i, int& s, int& d) {
    if (g_is64) {
        const long long* e = (const long long*)edges;
        s = (int)e[i]; d = (int)e[NE + i];
    } else {
        const int* e = (const int*)edges;
        s = e[i]; d = e[NE + i];
    }
}
__global__ void k_hist(const void* __restrict__ edges) {
    int i = blockIdx.x * blockDim.x + threadIdx.x;
    if (i >= NE) return;
    int s, d; load_edge(edges, i, s, d);
    atomicAdd(&g_deg[d], 1);
}
__global__ __launch_bounds__(256) void k_scan1() {
    __shared__ int wsum[8], wbase[8];
    int b = blockIdx.x, tid = threadIdx.x;
    int base = b * 1024 + tid * 4;
    int v0 = 0, v1 = 0, v2 = 0, v3 = 0;
    if (base + 3 < NN) {
        int4 t = *(const int4*)&g_deg[base];
        v0 = t.x; v1 = t.y; v2 = t.z; v3 = t.w;
    } else {
        if (base + 0 < NN) v0 = g_deg[base + 0];
        if (base + 1 < NN) v1 = g_deg[base + 1];
        if (base + 2 < NN) v2 = g_deg[base + 2];
        if (base + 3 < NN) v3 = g_deg[base + 3];
    }
    int s = v0 + v1 + v2 + v3;
    int lane = tid & 31, w = tid >> 5;
    int x = s;
#pragma unroll
    for (int off = 1; off < 32; off <<= 1) {
        int t = __shfl_up_sync(0xffffffffu, x, off);
        if (lane >= off) x += t;
    }
    if (lane == 31) wsum[w] = x;
    __syncthreads();
    if (tid == 0) {
        int run = 0;
#pragma unroll
        for (int i = 0; i < 8; i++) { wbase[i] = run; run += wsum[i]; }
        g_blksum[b] = run;
    }
    __syncthreads();
    int ex = wbase[w] + x - s;
    if (base + 0 < NN) g_rowstart[base + 0] = ex;
    if (base + 1 < NN) g_rowstart[base + 1] = ex + v0;
    if (base + 2 < NN) g_rowstart[base + 2] = ex + v0 + v1;
    if (base + 3 < NN) g_rowstart[base + 3] = ex + v0 + v1 + v2;
}
__global__ __launch_bounds__(128) void k_scan2() {
    __shared__ int sh[NBLK1];
    int tid = threadIdx.x;
    if (tid < NBLK1) sh[tid] = g_blksum[tid];
    __syncthreads();
    if (tid == 0) {
        int run = 0;
        for (int i = 0; i < NBLK1; i++) { int t = sh[i]; sh[i] = run; run += t; }
    }
    __syncthreads();
    if (tid < NBLK1) g_blksum[tid] = sh[tid];
}
__global__ void k_scan3() {
    int i = blockIdx.x * blockDim.x + threadIdx.x;
    if (i >= NN) return;
    int rs = g_rowstart[i] + g_blksum[i >> 10];
    g_rowstart[i] = rs;
    g_cursor[i] = rs;
    g_dinv[i] = rsqrtf((float)g_deg[i] + 1.0f);
    if (i == 0) g_rowstart[NN] = NE;
}
__global__ void k_fill(const void* __restrict__ edges) {
    int i = blockIdx.x * blockDim.x + threadIdx.x;
    if (i >= NE) return;
    int s, d; load_edge(edges, i, s, d);
    int pos = atomicAdd(&g_cursor[d], 1);
    g_esrc[pos] = s;
}

// ---------------------------------------------------------------------------
extern "C" void kernel_launch(void* const* d_in, const int* in_sizes, int n_in,
                              void* d_out, int out_size) {
    const float* user = (const float*)d_in[0];
    const float* prod = (const float*)d_in[1];
    const void*  edges = d_in[2];
    const float* Wu = (const float*)d_in[3];
    const float* bu = (const float*)d_in[4];
    const float* Wp = (const float*)d_in[5];
    const float* bp = (const float*)d_in[6];
    const float* W1 = (const float*)d_in[7];
    const float* b1 = (const float*)d_in[8];
    const float* W2 = (const float*)d_in[9];
    const float* b2 = (const float*)d_in[10];
    const float* W3 = (const float*)d_in[11];
    const float* b3 = (const float*)d_in[12];
    const float* Wo = (const float*)d_in[13];
    const float* bo = (const float*)d_in[14];
    float* out = (float*)d_out;

    __half *px = nullptr, *pya = nullptr, *pyb = nullptr;
    uint32_t* pw = nullptr;
    cudaGetSymbolAddress((void**)&px, g_x);
    cudaGetSymbolAddress((void**)&pya, g_ya);
    cudaGetSymbolAddress((void**)&pyb, g_yb);
    cudaGetSymbolAddress((void**)&pw, g_wfrag);

    const int smemU = (128 * 36 + 4 * 1024) * 4;   // 34816
    const int smemP = (128 * 60 + 7 * 1024) * 4;   // 59392
    const int smemL = (128 * 68 + 8 * 1024) * 4;   // 67584
    cudaFuncSetAttribute(k_gemm<4, 36, true, 64>,
        cudaFuncAttributeMaxDynamicSharedMemorySize, smemU);
    cudaFuncSetAttribute(k_gemm<7, 60, true, 100>,
        cudaFuncAttributeMaxDynamicSharedMemorySize, smemP);
    cudaFuncSetAttribute(k_gemm<8, 68, false, 128>,
        cudaFuncAttributeMaxDynamicSharedMemorySize, smemL);
    cudaFuncSetAttribute(k_fgemm,
        cudaFuncAttributeMaxDynamicSharedMemorySize, smemL);

    // fork point for CSR side chain
    cudaEventRecord(g_side.evFork, 0);
    cudaStreamWaitEvent(g_side.s, g_side.evFork, 0);

    // main stream: weight fragments + GEMM chain
    k_wfrag<<<36, 256>>>(Wu, Wp, W1, W2, W3, Wo);
    k_gemm<4, 36, true, 64><<<(N_USERS + 127) / 128, 256, smemU>>>(
        user, N_USERS, pw + OFF_WU, bu, px);
    k_gemm<7, 60, true, 100><<<(N_PRODS + 127) / 128, 256, smemP>>>(
        prod, N_PRODS, pw + OFF_WP, bp, px + (size_t)N_USERS * HDIM);
    k_gemm<8, 68, false, 128><<<(NN + 127) / 128, 256, smemL>>>(
        px, NN, pw + OFF_W1, nullptr, pya);

    // side stream: CSR build (overlaps the GEMM chain above)
    k_prep<<<(NN + 255) / 256, 256, 0, g_side.s>>>(edges);
    k_hist<<<(NE + 255) / 256, 256, 0, g_side.s>>>(edges);
    k_scan1<<<NBLK1, 256, 0, g_side.s>>>();
    k_scan2<<<1, 128, 0, g_side.s>>>();
    k_scan3<<<(NN + 255) / 256, 256, 0, g_side.s>>>();
    k_fill<<<(NE + 255) / 256, 256, 0, g_side.s>>>(edges);
    cudaEventRecord(g_side.evJoin, g_side.s);

    // join: fused layers need CSR + layer-1 y
    cudaStreamWaitEvent(0, g_side.evJoin, 0);

    // fused gather+GEMM layers (double-buffered y)
    k_fgemm<<<(NN + 127) / 128, 256, smemL>>>(pya, b1, pw + OFF_W2, pyb);
    k_fgemm<<<(NN + 127) / 128, 256, smemL>>>(pyb, b2, pw + OFF_W3, pya);
    // fused gather + output GEMM
    k_fout<<<(NN + 127) / 128, 256>>>(pya, b3, pw + OFF_WO, bo, out);
}

// round 16
// speedup vs baseline: 1.4582x; 1.4582x over previous
#include <cuda_runtime.h>
#include <cuda_fp16.h>
#include <cstdint>
#include <cstddef>

#define N_USERS 50000
#define N_PRODS 50000
#define NN      100000
#define NE      600000
#define HDIM    128
#define ODIM    16
#define NBLK1   98        // ceil(NN/1024)

// Scratch (__device__ globals: allocation-free rule)
__device__ __half   g_x[(size_t)NN * HDIM];
__device__ __half   g_y[(size_t)NN * HDIM];
__device__ float    g_dinv[NN];
__device__ int      g_deg[NN];
__device__ int      g_rowstart[NN + 1];
__device__ int      g_cursor[NN];
__device__ int      g_esrc[NE];
__device__ int      g_blksum[NBLK1];
__device__ int      g_is64;
// f16 B fragments: Wu@0(4096), Wp@4096(7168), W1@11264, W2@19456, W3@27648 (8192 ea), Wo@35840(1024)
__device__ uint32_t g_wfrag[36864];

#define OFF_WU 0
#define OFF_WP 4096
#define OFF_W1 11264
#define OFF_W2 19456
#define OFF_W3 27648
#define OFF_WO 35840

// Side streams + events (static-init; reused every call -> deterministic).
struct SideStreams {
    cudaStream_t s1 = nullptr, s2 = nullptr;
    cudaEvent_t evFork1 = nullptr, evJoin1 = nullptr;
    cudaEvent_t evFork2 = nullptr, evJoin2 = nullptr;
    SideStreams() {
        cudaStreamCreateWithFlags(&s1, cudaStreamNonBlocking);
        cudaStreamCreateWithFlags(&s2, cudaStreamNonBlocking);
        cudaEventCreateWithFlags(&evFork1, cudaEventDisableTiming);
        cudaEventCreateWithFlags(&evJoin1, cudaEventDisableTiming);
        cudaEventCreateWithFlags(&evFork2, cudaEventDisableTiming);
        cudaEventCreateWithFlags(&evJoin2, cudaEventDisableTiming);
    }
};
static SideStreams g_side;

// ---------------------------------------------------------------------------
// helpers (sm_80-class PTX only)
// ---------------------------------------------------------------------------
__device__ __forceinline__ uint32_t packh2(float lo, float hi) {
    __half2 h = __floats2half2_rn(lo, hi);
    return *reinterpret_cast<uint32_t*>(&h);
}
__device__ __forceinline__ void mma_f16(float* c, const uint32_t* a, const uint32_t* b) {
    asm volatile(
        "mma.sync.aligned.m16n8k16.row.col.f32.f16.f16.f32 "
        "{%0,%1,%2,%3}, {%4,%5,%6,%7}, {%8,%9}, {%0,%1,%2,%3};"
        : "+f"(c[0]), "+f"(c[1]), "+f"(c[2]), "+f"(c[3])
        : "r"(a[0]), "r"(a[1]), "r"(a[2]), "r"(a[3]), "r"(b[0]), "r"(b[1]));
}
__device__ __forceinline__ void h4_to_f4(uint2 t, float4& f) {
    float2 a = __half22float2(*reinterpret_cast<__half2*>(&t.x));
    float2 b = __half22float2(*reinterpret_cast<__half2*>(&t.y));
    f.x = a.x; f.y = a.y; f.z = b.x; f.w = b.y;
}

// ---------------------------------------------------------------------------
// Precompute f16 B fragments for all 6 weights.
// m16n8k16 B tile word w: reg=w&1, lane=w>>1, n'=lane>>2, tg=lane&3;
// word = {B[tg*2+reg*8][n'], B[tg*2+1+reg*8][n']}. Tile (k16,nt) at (k16*NT+nt)*64.
// ---------------------------------------------------------------------------
__global__ __launch_bounds__(256) void k_wfrag(
    const float* __restrict__ Wu, const float* __restrict__ Wp,
    const float* __restrict__ W1, const float* __restrict__ W2,
    const float* __restrict__ W3, const float* __restrict__ Wo)
{
    const int nblk[6] = {4, 7, 8, 8, 8, 1};
    const int offs[6] = {OFF_WU, OFF_WP, OFF_W1, OFF_W2, OFF_W3, OFF_WO};
    const int kds[6]  = {64, 100, 128, 128, 128, 128};
    int b = blockIdx.x, slot = 0;
    while (slot < 6 && b >= nblk[slot]) { b -= nblk[slot]; slot++; }
    if (slot >= 6) return;
    const float* W = (slot == 0) ? Wu : (slot == 1) ? Wp : (slot == 2) ? W1
                   : (slot == 3) ? W2 : (slot == 4) ? W3 : Wo;
    const int Kdim = kds[slot];
    uint32_t* dst = g_wfrag + offs[slot];
    if (slot < 5) {
#pragma unroll
        for (int i = 0; i < 4; i++) {
            int w = b * 1024 + threadIdx.x + i * 256;
            int nt = (w >> 6) & 15;
            int widx = w & 63;
            int reg = widx & 1, lane = widx >> 1;
            int n = nt * 8 + (lane >> 2), tg = lane & 3;
            int k = (w >> 10) * 16 + tg * 2 + reg * 8;
            float lo = (k     < Kdim) ? W[(size_t)k * HDIM + n] : 0.f;
            float hi = (k + 1 < Kdim) ? W[(size_t)(k + 1) * HDIM + n] : 0.f;
            dst[w] = packh2(lo, hi);
        }
    } else {
#pragma unroll
        for (int i = 0; i < 4; i++) {
            int w = threadIdx.x + i * 256;
            int k16 = w >> 7, r = w & 127;
            int nt = (r >> 6) & 1;
            int widx = r & 63;
            int reg = widx & 1, lane = widx >> 1;
            int n = nt * 8 + (lane >> 2), tg = lane & 3;
            int k = k16 * 16 + tg * 2 + reg * 8;
            dst[w] = packh2(W[(size_t)k * ODIM + n], W[(size_t)(k + 1) * ODIM + n]);
        }
    }
}

// ---------------------------------------------------------------------------
// Unified f16 m16n8k16 GEMM (R12 config): 256 thr, 128x128 CTA tile,
// warp tile 32x64, 2 CTAs/SM. A in SMEM (row stride SW, SW%8==4 ->
// conflict-free LDS.32), B fragments in SMEM (conflict-free LDS.64).
// F32IN: stage fp32 A (lda=KDIM) packed to f16. else raw fp16 copy (lda=128).
// ---------------------------------------------------------------------------
template<int K16, int SW, bool F32IN, int KDIM>
__global__ __launch_bounds__(256, 2) void k_gemm(
    const void* __restrict__ Av, int M,
    const uint32_t* __restrict__ Bfrag, const float* __restrict__ bias,
    __half* __restrict__ out)
{
    extern __shared__ uint32_t smem[];
    uint32_t* sA = smem;                 // 128 * SW words
    uint32_t* sB = smem + 128 * SW;      // K16 * 1024 words

    const int tid = threadIdx.x;
    const int wid = tid >> 5;
    const int lane = tid & 31;
    const int m0 = blockIdx.x * 128;
    const int wm = wid & 3;
    const int wn = wid >> 2;
    const int g = lane >> 2, tg = lane & 3;

#pragma unroll
    for (int it = 0; it < K16; it++) {
        int idx = tid + it * 256;
        ((uint4*)sB)[idx] = ((const uint4*)Bfrag)[idx];
    }

    if (F32IN) {
        const float* A = (const float*)Av;
        constexpr int KPAD = K16 * 16;
        constexpr int NC4 = KPAD / 4;
#pragma unroll
        for (int it = 0; it < 128 * NC4 / 256; it++) {
            int idx4 = tid + it * 256;
            int r = idx4 / NC4;
            int c4 = (idx4 - r * NC4) * 4;
            int gm = m0 + r;
            float4 v = make_float4(0.f, 0.f, 0.f, 0.f);
            if (gm < M && c4 < KDIM)
                v = *(const float4*)&A[(size_t)gm * KDIM + c4];
            uint32_t* p = sA + r * SW + c4 / 2;
            p[0] = packh2(v.x, v.y);
            p[1] = packh2(v.z, v.w);
        }
    } else {
        const __half* A = (const __half*)Av;
#pragma unroll
        for (int it = 0; it < 8; it++) {
            int idx = tid + it * 256;
            int r = idx >> 4, u = idx & 15;
            int gm = m0 + r;
            uint4 v = make_uint4(0u, 0u, 0u, 0u);
            if (gm < M) v = *(const uint4*)&A[(size_t)gm * HDIM + u * 8];
            *(uint4*)(sA + r * SW + u * 4) = v;
        }
    }
    __syncthreads();

    float acc[2][8][4];
#pragma unroll
    for (int mt = 0; mt < 2; mt++)
#pragma unroll
        for (int nt = 0; nt < 8; nt++)
#pragma unroll
            for (int j = 0; j < 4; j++) acc[mt][nt][j] = 0.f;

    const uint32_t* sAr = sA + (wm * 32 + g) * SW + tg;
    const uint2* Bw = (const uint2*)(sB + (wn * 8) * 64) + lane;

#pragma unroll
    for (int k16 = 0; k16 < K16; k16++) {
        const int c0 = k16 * 8;
        uint32_t a[2][4];
#pragma unroll
        for (int mt = 0; mt < 2; mt++) {
            const uint32_t* p = sAr + mt * 16 * SW;
            a[mt][0] = p[c0];
            a[mt][1] = p[8 * SW + c0];
            a[mt][2] = p[c0 + 4];
            a[mt][3] = p[8 * SW + c0 + 4];
        }
        uint32_t b[8][2];
#pragma unroll
        for (int nt = 0; nt < 8; nt++) {
            uint2 t = Bw[(k16 * 16 + nt) * 32];
            b[nt][0] = t.x; b[nt][1] = t.y;
        }
#pragma unroll
        for (int mt = 0; mt < 2; mt++)
#pragma unroll
            for (int nt = 0; nt < 8; nt++)
                mma_f16(acc[mt][nt], a[mt], b[nt]);
    }

    const int rbase = m0 + wm * 32 + g;
#pragma unroll
    for (int mt = 0; mt < 2; mt++) {
        int r0 = rbase + mt * 16;
        int r1 = r0 + 8;
#pragma unroll
        for (int nt = 0; nt < 8; nt++) {
            int col = wn * 64 + nt * 8 + tg * 2;
            float bx = 0.f, by = 0.f;
            if (bias) {
                float2 bb = *(const float2*)&bias[col];
                bx = bb.x; by = bb.y;
            }
            if (r0 < M)
                *(__half2*)&out[(size_t)r0 * HDIM + col] =
                    __floats2half2_rn(acc[mt][nt][0] + bx, acc[mt][nt][1] + by);
            if (r1 < M)
                *(__half2*)&out[(size_t)r1 * HDIM + col] =
                    __floats2half2_rn(acc[mt][nt][2] + bx, acc[mt][nt][3] + by);
        }
    }
}

// ---------------------------------------------------------------------------
// Edge detect + degree zero (merged) + CSR build
// ---------------------------------------------------------------------------
__global__ void k_prep(const void* __restrict__ edges) {
    int i = blockIdx.x * blockDim.x + threadIdx.x;
    if (i < NN) g_deg[i] = 0;
    if (i == 0) {
        const unsigned int* w = (const unsigned int*)edges;
        int is64 = 1;
        for (int j = 0; j < 64; j++)
            if (w[2 * j + 1] != 0u) { is64 = 0; break; }
        g_is64 = is64;
    }
}
__device__ __forceinline__ void load_edge(const void* edges, int i, int& s, int& d) {
    if (g_is64) {
        const long long* e = (const long long*)edges;
        s = (int)e[i]; d = (int)e[NE + i];
    } else {
        const int* e = (const int*)edges;
        s = e[i]; d = e[NE + i];
    }
}
__global__ void k_hist(const void* __restrict__ edges) {
    int i = blockIdx.x * blockDim.x + threadIdx.x;
    if (i >= NE) return;
    int s, d; load_edge(edges, i, s, d);
    atomicAdd(&g_deg[d], 1);
}
__global__ __launch_bounds__(256) void k_scan1() {
    __shared__ int wsum[8], wbase[8];
    int b = blockIdx.x, tid = threadIdx.x;
    int base = b * 1024 + tid * 4;
    int v0 = 0, v1 = 0, v2 = 0, v3 = 0;
    if (base + 3 < NN) {
        int4 t = *(const int4*)&g_deg[base];
        v0 = t.x; v1 = t.y; v2 = t.z; v3 = t.w;
    } else {
        if (base + 0 < NN) v0 = g_deg[base + 0];
        if (base + 1 < NN) v1 = g_deg[base + 1];
        if (base + 2 < NN) v2 = g_deg[base + 2];
        if (base + 3 < NN) v3 = g_deg[base + 3];
    }
    int s = v0 + v1 + v2 + v3;
    int lane = tid & 31, w = tid >> 5;
    int x = s;
#pragma unroll
    for (int off = 1; off < 32; off <<= 1) {
        int t = __shfl_up_sync(0xffffffffu, x, off);
        if (lane >= off) x += t;
    }
    if (lane == 31) wsum[w] = x;
    __syncthreads();
    if (tid == 0) {
        int run = 0;
#pragma unroll
        for (int i = 0; i < 8; i++) { wbase[i] = run; run += wsum[i]; }
        g_blksum[b] = run;
    }
    __syncthreads();
    int ex = wbase[w] + x - s;
    if (base + 0 < NN) g_rowstart[base + 0] = ex;
    if (base + 1 < NN) g_rowstart[base + 1] = ex + v0;
    if (base + 2 < NN) g_rowstart[base + 2] = ex + v0 + v1;
    if (base + 3 < NN) g_rowstart[base + 3] = ex + v0 + v1 + v2;
}
__global__ __launch_bounds__(128) void k_scan2() {
    __shared__ int sh[NBLK1];
    int tid = threadIdx.x;
    if (tid < NBLK1) sh[tid] = g_blksum[tid];
    __syncthreads();
    if (tid == 0) {
        int run = 0;
        for (int i = 0; i < NBLK1; i++) { int t = sh[i]; sh[i] = run; run += t; }
    }
    __syncthreads();
    if (tid < NBLK1) g_blksum[tid] = sh[tid];
}
__global__ void k_scan3() {
    int i = blockIdx.x * blockDim.x + threadIdx.x;
    if (i >= NN) return;
    int rs = g_rowstart[i] + g_blksum[i >> 10];
    g_rowstart[i] = rs;
    g_cursor[i] = rs;
    g_dinv[i] = rsqrtf((float)g_deg[i] + 1.0f);
    if (i == 0) g_rowstart[NN] = NE;
}
__global__ void k_fill(const void* __restrict__ edges) {
    int i = blockIdx.x * blockDim.x + threadIdx.x;
    if (i >= NE) return;
    int s, d; load_edge(edges, i, s, d);
    int pos = atomicAdd(&g_cursor[d], 1);
    g_esrc[pos] = s;
}

// ---------------------------------------------------------------------------
// CSR gather + fused ReLU, fp16 in/out. Lane covers cols lane*4..lane*4+3.
// ---------------------------------------------------------------------------
__global__ __launch_bounds__(256) void k_gather(const float* __restrict__ bias) {
    int gt = blockIdx.x * blockDim.x + threadIdx.x;
    int node = gt >> 5;
    int lane = gt & 31;
    if (node >= NN) return;

    const int co = lane * 4;
    float dd = g_dinv[node];
    float4 acc;
    {
        uint2 t = *(const uint2*)&g_y[(size_t)node * HDIM + co];
        h4_to_f4(t, acc);
        acc.x *= dd; acc.y *= dd; acc.z *= dd; acc.w *= dd;
    }

    int e = g_rowstart[node];
    const int end = g_rowstart[node + 1];
    for (; e + 4 <= end; e += 4) {
        int s0 = g_esrc[e], s1 = g_esrc[e + 1], s2 = g_esrc[e + 2], s3 = g_esrc[e + 3];
        float n0 = g_dinv[s0], n1 = g_dinv[s1], n2 = g_dinv[s2], n3 = g_dinv[s3];
        uint2 t0 = *(const uint2*)&g_y[(size_t)s0 * HDIM + co];
        uint2 t1 = *(const uint2*)&g_y[(size_t)s1 * HDIM + co];
        uint2 t2 = *(const uint2*)&g_y[(size_t)s2 * HDIM + co];
        uint2 t3 = *(const uint2*)&g_y[(size_t)s3 * HDIM + co];
        float4 a, b, c, d;
        h4_to_f4(t0, a); h4_to_f4(t1, b); h4_to_f4(t2, c); h4_to_f4(t3, d);
        acc.x += a.x * n0 + b.x * n1 + c.x * n2 + d.x * n3;
        acc.y += a.y * n0 + b.y * n1 + c.y * n2 + d.y * n3;
        acc.z += a.z * n0 + b.z * n1 + c.z * n2 + d.z * n3;
        acc.w += a.w * n0 + b.w * n1 + c.w * n2 + d.w * n3;
    }
    for (; e < end; e++) {
        int s = g_esrc[e];
        float ns = g_dinv[s];
        uint2 t = *(const uint2*)&g_y[(size_t)s * HDIM + co];
        float4 a; h4_to_f4(t, a);
        acc.x += a.x * ns; acc.y += a.y * ns; acc.z += a.z * ns; acc.w += a.w * ns;
    }
    float4 bb = *(const float4*)&bias[co];
    float ox = fmaxf(acc.x * dd + bb.x, 0.f);
    float oy = fmaxf(acc.y * dd + bb.y, 0.f);
    float oz = fmaxf(acc.z * dd + bb.z, 0.f);
    float ow = fmaxf(acc.w * dd + bb.w, 0.f);
    uint2 o;
    *reinterpret_cast<__half2*>(&o.x) = __floats2half2_rn(ox, oy);
    *reinterpret_cast<__half2*>(&o.y) = __floats2half2_rn(oz, ow);
    *(uint2*)&g_x[(size_t)node * HDIM + co] = o;
}

// ---------------------------------------------------------------------------
// Output GEMM (f16 mma): out[NN,16] = g_x @ Wo + bo.
// CTA 128 rows, 8 warps, warp tile 16x16. Wo fragments staged in SMEM too.
// ---------------------------------------------------------------------------
__global__ __launch_bounds__(256) void k_out(
    const uint32_t* __restrict__ Bfrag, const float* __restrict__ bo,
    float* __restrict__ out)
{
    constexpr int SW = 68;
    __shared__ uint32_t sA[128 * SW];
    __shared__ uint32_t sB[1024];
    const int tid = threadIdx.x;
    const int wid = tid >> 5;
    const int lane = tid & 31;
    const int m0 = blockIdx.x * 128;
    const int g = lane >> 2, tg = lane & 3;

    ((uint4*)sB)[tid] = ((const uint4*)Bfrag)[tid];
#pragma unroll
    for (int it = 0; it < 8; it++) {
        int idx = tid + it * 256;
        int r = idx >> 4, u = idx & 15;
        int gm = m0 + r;
        uint4 v = make_uint4(0u, 0u, 0u, 0u);
        if (gm < NN) v = *(const uint4*)&g_x[(size_t)gm * HDIM + u * 8];
        *(uint4*)(sA + r * SW + u * 4) = v;
    }
    __syncthreads();

    float acc[2][4];
#pragma unroll
    for (int nt = 0; nt < 2; nt++)
#pragma unroll
        for (int j = 0; j < 4; j++) acc[nt][j] = 0.f;

    const uint32_t* sAr = sA + (wid * 16 + g) * SW + tg;
    const uint2* Bw = (const uint2*)sB + lane;

#pragma unroll
    for (int k16 = 0; k16 < 8; k16++) {
        const int c0 = k16 * 8;
        uint32_t a[4];
        a[0] = sAr[c0];
        a[1] = sAr[8 * SW + c0];
        a[2] = sAr[c0 + 4];
        a[3] = sAr[8 * SW + c0 + 4];
#pragma unroll
        for (int nt = 0; nt < 2; nt++) {
            uint2 t = Bw[(k16 * 2 + nt) * 32];
            uint32_t b[2] = {t.x, t.y};
            mma_f16(acc[nt], a, b);
        }
    }

    const int r0 = m0 + wid * 16 + g;
    const int r1 = r0 + 8;
#pragma unroll
    for (int nt = 0; nt < 2; nt++) {
        int col = nt * 8 + tg * 2;
        float2 bb = *(const float2*)&bo[col];
        if (r0 < NN) {
            out[(size_t)r0 * ODIM + col + 0] = acc[nt][0] + bb.x;
            out[(size_t)r0 * ODIM + col + 1] = acc[nt][1] + bb.y;
        }
        if (r1 < NN) {
            out[(size_t)r1 * ODIM + col + 0] = acc[nt][2] + bb.x;
            out[(size_t)r1 * ODIM + col + 1] = acc[nt][3] + bb.y;
        }
    }
}

// ---------------------------------------------------------------------------
extern "C" void kernel_launch(void* const* d_in, const int* in_sizes, int n_in,
                              void* d_out, int out_size) {
    const float* user = (const float*)d_in[0];
    const float* prod = (const float*)d_in[1];
    const void*  edges = d_in[2];
    const float* Wu = (const float*)d_in[3];
    const float* bu = (const float*)d_in[4];
    const float* Wp = (const float*)d_in[5];
    const float* bp = (const float*)d_in[6];
    const float* W1 = (const float*)d_in[7];
    const float* b1 = (const float*)d_in[8];
    const float* W2 = (const float*)d_in[9];
    const float* b2 = (const float*)d_in[10];
    const float* W3 = (const float*)d_in[11];
    const float* b3 = (const float*)d_in[12];
    const float* Wo = (const float*)d_in[13];
    const float* bo = (const float*)d_in[14];
    float* out = (float*)d_out;

    __half *px = nullptr, *py = nullptr;
    uint32_t* pw = nullptr;
    cudaGetSymbolAddress((void**)&px, g_x);
    cudaGetSymbolAddress((void**)&py, g_y);
    cudaGetSymbolAddress((void**)&pw, g_wfrag);

    const int smemU = (128 * 36 + 4 * 1024) * 4;   // 34816
    const int smemP = (128 * 60 + 7 * 1024) * 4;   // 59392
    const int smemL = (128 * 68 + 8 * 1024) * 4;   // 67584
    cudaFuncSetAttribute(k_gemm<4, 36, true, 64>,
        cudaFuncAttributeMaxDynamicSharedMemorySize, smemU);
    cudaFuncSetAttribute(k_gemm<7, 60, true, 100>,
        cudaFuncAttributeMaxDynamicSharedMemorySize, smemP);
    cudaFuncSetAttribute(k_gemm<8, 68, false, 128>,
        cudaFuncAttributeMaxDynamicSharedMemorySize, smemL);

    // ---- fork 1: CSR build on side stream 1 (independent of GEMM path) ----
    cudaEventRecord(g_side.evFork1, 0);
    cudaStreamWaitEvent(g_side.s1, g_side.evFork1, 0);
    k_prep<<<(NN + 255) / 256, 256, 0, g_side.s1>>>(edges);
    k_hist<<<(NE + 255) / 256, 256, 0, g_side.s1>>>(edges);
    k_scan1<<<NBLK1, 256, 0, g_side.s1>>>();
    k_scan2<<<1, 128, 0, g_side.s1>>>();
    k_scan3<<<(NN + 255) / 256, 256, 0, g_side.s1>>>();
    k_fill<<<(NE + 255) / 256, 256, 0, g_side.s1>>>(edges);
    cudaEventRecord(g_side.evJoin1, g_side.s1);

    // ---- main stream: weight fragments ----
    k_wfrag<<<36, 256>>>(Wu, Wp, W1, W2, W3, Wo);

    // ---- fork 2: prod input transform on side stream 2 (needs wfrag only) ----
    cudaEventRecord(g_side.evFork2, 0);
    cudaStreamWaitEvent(g_side.s2, g_side.evFork2, 0);
    k_gemm<7, 60, true, 100><<<(N_PRODS + 127) / 128, 256, smemP, g_side.s2>>>(
        prod, N_PRODS, pw + OFF_WP, bp, px + (size_t)N_USERS * HDIM);
    cudaEventRecord(g_side.evJoin2, g_side.s2);

    // main: user input transform (overlaps prod)
    k_gemm<4, 36, true, 64><<<(N_USERS + 127) / 128, 256, smemU>>>(
        user, N_USERS, pw + OFF_WU, bu, px);

    // join 2: layer-1 GEMM needs full g_x
    cudaStreamWaitEvent(0, g_side.evJoin2, 0);
    k_gemm<8, 68, false, 128><<<(NN + 127) / 128, 256, smemL>>>(
        px, NN, pw + OFF_W1, nullptr, py);

    // join 1: gather needs CSR + layer-1 y
    cudaStreamWaitEvent(0, g_side.evJoin1, 0);
    k_gather<<<(NN * 32 + 255) / 256, 256>>>(b1);

    // layers 2,3
    k_gemm<8, 68, false, 128><<<(NN + 127) / 128, 256, smemL>>>(
        px, NN, pw + OFF_W2, nullptr, py);
    k_gather<<<(NN * 32 + 255) / 256, 256>>>(b2);

    k_gemm<8, 68, false, 128><<<(NN + 127) / 128, 256, smemL>>>(
        px, NN, pw + OFF_W3, nullptr, py);
    k_gather<<<(NN * 32 + 255) / 256, 256>>>(b3);

    // output GEMM (fixed grid: 128 rows per CTA)
    k_out<<<(NN + 127) / 128, 256>>>(pw + OFF_WO, bo, out);
}